// round 16
// baseline (speedup 1.0000x reference)
#include <cuda_runtime.h>
#include <cuda_fp16.h>
#include <stdint.h>

// out[B,N] = x[B,K] @ W[K,N];  B=65536, K=512, N=64, fp32.
// Persistent fp16 HMMA. grid=128, 256 threads (8 warps). Each warp owns
// 32-row tiles x all 64 cols (2 m-tiles per MMA step -> W-fragment smem reads
// halved per x-byte). 2048 tiles / 1024 warp-slots = exactly 2 tiles each.
// Per-warp private 5-slot x pipeline (4KB fp32 slots, cp.async), uniform
// commit cadence. W fp16 swizzled smem (64KB) converted once per CTA.

#define BATCH   65536
#define KDIM    512
#define NDIM    64
#define THREADS 256
#define NWARP   8
#define GRID    128
#define NTILES  (BATCH / 32)        // 2048
#define RTSTRIDE (NWARP * GRID)     // 1024 -> exactly 2 tiles per warp
#define NSTAGE  5
#define TOTALF  32                  // fill half-chunks per warp (2 tiles x 16)

#define SM_W    0                   // 64KB fp16 swizzled W
#define SM_X    65536               // warp w slot s: + w*(NSTAGE*4096) + s*4096
#define SMEM_TOTAL (65536 + NWARP * NSTAGE * 4096)   // 229376

__device__ __forceinline__ void mma_f16(float* d, const uint32_t* a, const uint32_t* b) {
    asm volatile(
        "mma.sync.aligned.m16n8k16.row.col.f32.f16.f16.f32 "
        "{%0,%1,%2,%3}, {%4,%5,%6,%7}, {%8,%9}, {%0,%1,%2,%3};\n"
        : "+f"(d[0]), "+f"(d[1]), "+f"(d[2]), "+f"(d[3])
        : "r"(a[0]), "r"(a[1]), "r"(a[2]), "r"(a[3]), "r"(b[0]), "r"(b[1]));
}

__device__ __forceinline__ void ldsm_x4(uint32_t* r, uint32_t saddr) {
    asm volatile("ldmatrix.sync.aligned.m8n8.x4.shared.b16 {%0,%1,%2,%3}, [%4];"
        : "=r"(r[0]), "=r"(r[1]), "=r"(r[2]), "=r"(r[3]) : "r"(saddr));
}

__device__ __forceinline__ void cpasync16(uint32_t saddr, const void* gptr) {
    asm volatile("cp.async.cg.shared.global [%0], [%1], 16;\n"
        :: "r"(saddr), "l"(gptr));
}
#define CP_COMMIT()  asm volatile("cp.async.commit_group;\n" ::: "memory")
#define CP_WAIT(N)   asm volatile("cp.async.wait_group %0;\n" :: "n"(N) : "memory")

__device__ __forceinline__ uint32_t cvt2(float2 v) {
    __half2 h = __floats2half2_rn(v.x, v.y);
    return *reinterpret_cast<uint32_t*>(&h);
}

__device__ __forceinline__ float2 lds64(uint32_t saddr) {
    float2 v;
    asm volatile("ld.shared.v2.f32 {%0,%1}, [%2];"
        : "=f"(v.x), "=f"(v.y) : "r"(saddr));
    return v;
}

__global__ __launch_bounds__(THREADS, 1)
void NN_57844619543085_kernel(const float* __restrict__ x,
                              const float* __restrict__ W,
                              float* __restrict__ out) {
    extern __shared__ __align__(1024) unsigned char sm[];
    const uint32_t smb = (uint32_t)__cvta_generic_to_shared(sm);

    const int t    = threadIdx.x;
    const int lane = t & 31;
    const int warp = t >> 5;

    // ---- warp's tiles: rt0 and rt0 + 1024 (exactly 2, perfectly balanced) --
    const int rt0 = warp * GRID + blockIdx.x;     // 0..1023

    // ---- fill addressing: slot = 32 rows x 32 k fp32 = 4KB ----
    const int rbase = lane >> 3;                  // 0..3
    const int g     = lane & 7;                   // 16B granule in 128B k-row
    const uint32_t fill_off = (uint32_t)rbase * 128
                            + (uint32_t)((g * 16) ^ (rbase << 5));
    const uint32_t xw = smb + SM_X + warp * (NSTAGE * 4096);

    const float* fsrc = x + ((size_t)rt0 * 32 + rbase) * KDIM + g * 4;
    int h_f = 0, sf = 0, ff = 0;
    const size_t tile_jump = (size_t)RTSTRIDE * 32 * KDIM;   // 2nd tile offset

#define ADV()                                                                  \
    {                                                                          \
        if (ff < TOTALF) {                                                     \
            uint32_t d_ = xw + sf * 4096 + fill_off;                           \
            const float* s_ = fsrc + h_f * 32;                                 \
            cpasync16(d_,         s_);                                         \
            cpasync16(d_ + 512,   s_ + 4  * KDIM);                             \
            cpasync16(d_ + 1024,  s_ + 8  * KDIM);                             \
            cpasync16(d_ + 1536,  s_ + 12 * KDIM);                             \
            cpasync16(d_ + 2048,  s_ + 16 * KDIM);                             \
            cpasync16(d_ + 2560,  s_ + 20 * KDIM);                             \
            cpasync16(d_ + 3072,  s_ + 24 * KDIM);                             \
            cpasync16(d_ + 3584,  s_ + 28 * KDIM);                             \
        }                                                                      \
        CP_COMMIT();                                                           \
        ++ff; sf = (sf == NSTAGE - 1) ? 0 : sf + 1;                            \
        if (++h_f == 16) { h_f = 0; fsrc += tile_jump; }                       \
    }

    // ---- prologue: 5 slots in flight ----
    ADV(); ADV(); ADV(); ADV(); ADV();

    // ---- W conversion: fp32 gmem -> fp16 swizzled smem (overlaps fills) ----
    {
        const int wn_ = t & 63;
        const int wq_ = t >> 6;                   // 0..3, 128 k each
        const uint32_t wrow = smb + SM_W + wn_ * 128;
        const int nsw = (wn_ & 7) << 4;
#pragma unroll 4
        for (int i = 0; i < 32; ++i) {
            int k = wq_ * 128 + i * 4;
            float f0 = __ldg(&W[(k + 0) * NDIM + wn_]);
            float f1 = __ldg(&W[(k + 1) * NDIM + wn_]);
            float f2 = __ldg(&W[(k + 2) * NDIM + wn_]);
            float f3 = __ldg(&W[(k + 3) * NDIM + wn_]);
            uint32_t p0 = cvt2(make_float2(f0, f1));
            uint32_t p1 = cvt2(make_float2(f2, f3));
            uint32_t off = (uint32_t)((k >> 6) * 8192)
                         + (uint32_t)(((k & 63) * 2) ^ nsw);
            asm volatile("st.shared.v2.b32 [%0], {%1,%2};"
                :: "r"(wrow + off), "r"(p0), "r"(p1) : "memory");
        }
    }

    // ---- consume addressing ----
    const int r  = lane >> 2;                     // 0..7
    const int c8 = (lane & 3) * 8;
    const uint32_t sxor = (uint32_t)((r & 3) << 5);
    const uint32_t o_lo[2] = { (uint32_t)(c8)      ^ sxor,
                               (uint32_t)(64 + c8) ^ sxor };
    const uint32_t o_hi[2] = { (uint32_t)(32 + c8) ^ sxor,
                               (uint32_t)(96 + c8) ^ sxor };
    const uint32_t rb[4] = { (uint32_t)r * 128,            // rows r      (mt0)
                             (uint32_t)(r + 8)  * 128,     // rows r+8    (mt0)
                             (uint32_t)(r + 16) * 128,     // rows r+16   (mt1)
                             (uint32_t)(r + 24) * 128 };   // rows r+24   (mt1)

    const int sub  = lane >> 3;
    const int lrow = lane & 7;

    float acc[2][8][4];
#pragma unroll
    for (int mt = 0; mt < 2; ++mt)
#pragma unroll
        for (int nt8 = 0; nt8 < 8; ++nt8)
#pragma unroll
            for (int q = 0; q < 4; ++q) acc[mt][nt8][q] = 0.0f;

    __syncthreads();   // W tile visible CTA-wide

    // one half-chunk (32 k = 2 k16 with LITERAL ksic KS0,KS1), 2 m-tiles
#define HALF(WB, KS0, KS1)                                                     \
    {                                                                          \
        CP_WAIT(NSTAGE - 1);                                                   \
        __syncwarp();                                                          \
        const uint32_t xb = xw + slot * 4096;                                  \
        uint32_t A[2][2][4];                                                   \
        _Pragma("unroll")                                                      \
        for (int j = 0; j < 2; ++j)                                            \
        _Pragma("unroll")                                                      \
        for (int mt = 0; mt < 2; ++mt) {                                       \
            A[j][mt][0] = cvt2(lds64(xb + rb[2*mt]   + o_lo[j]));              \
            A[j][mt][1] = cvt2(lds64(xb + rb[2*mt+1] + o_lo[j]));              \
            A[j][mt][2] = cvt2(lds64(xb + rb[2*mt]   + o_hi[j]));              \
            A[j][mt][3] = cvt2(lds64(xb + rb[2*mt+1] + o_hi[j]));              \
        }                                                                      \
        ADV();                                                                 \
        uint32_t b[8][2];                                                      \
        _Pragma("unroll")                                                      \
        for (int p = 0; p < 4; ++p) {                                          \
            int n = (2 * p + (sub >> 1)) * 8 + lrow;                           \
            uint32_t boff = (uint32_t)n * 128                                  \
                          + (((KS0) * 32 + (sub & 1) * 16) ^ (lrow << 4));     \
            uint32_t tmp[4];                                                   \
            ldsm_x4(tmp, (WB) + boff);                                         \
            b[2*p][0]   = tmp[0]; b[2*p][1]   = tmp[1];                        \
            b[2*p+1][0] = tmp[2]; b[2*p+1][1] = tmp[3];                        \
        }                                                                      \
        _Pragma("unroll")                                                      \
        for (int nt8 = 0; nt8 < 8; ++nt8) {                                    \
            mma_f16(acc[0][nt8], A[0][0], b[nt8]);                             \
            mma_f16(acc[1][nt8], A[0][1], b[nt8]);                             \
        }                                                                      \
        _Pragma("unroll")                                                      \
        for (int p = 0; p < 4; ++p) {                                          \
            int n = (2 * p + (sub >> 1)) * 8 + lrow;                           \
            uint32_t boff = (uint32_t)n * 128                                  \
                          + (((KS1) * 32 + (sub & 1) * 16) ^ (lrow << 4));     \
            uint32_t tmp[4];                                                   \
            ldsm_x4(tmp, (WB) + boff);                                         \
            b[2*p][0]   = tmp[0]; b[2*p][1]   = tmp[1];                        \
            b[2*p+1][0] = tmp[2]; b[2*p+1][1] = tmp[3];                        \
        }                                                                      \
        _Pragma("unroll")                                                      \
        for (int nt8 = 0; nt8 < 8; ++nt8) {                                    \
            mma_f16(acc[0][nt8], A[1][0], b[nt8]);                             \
            mma_f16(acc[1][nt8], A[1][1], b[nt8]);                             \
        }                                                                      \
        slot = (slot == NSTAGE - 1) ? 0 : slot + 1;                            \
    }

    int rt_c = rt0;
    int slot = 0;
#pragma unroll 1
    for (int f2 = 0; f2 < 16; ++f2) {             // 16 pairs = 32 half-chunks
        const uint32_t wbase = smb + SM_W + (uint32_t)(f2 & 7) * 8192;

        HALF(wbase, 0, 1);
        HALF(wbase, 2, 3);

        // ---- tile boundary: store 32 rows + reset ----
        if ((f2 & 7) == 7) {
#pragma unroll
            for (int mt = 0; mt < 2; ++mt) {
                const int arow = rt_c * 32 + mt * 16 + (lane >> 2);
#pragma unroll
                for (int nt8 = 0; nt8 < 8; ++nt8) {
                    int gcol = nt8 * 8 + (lane & 3) * 2;
                    __stcs((float2*)(out + (size_t)arow * NDIM + gcol),
                           make_float2(acc[mt][nt8][0], acc[mt][nt8][1]));
                    __stcs((float2*)(out + (size_t)(arow + 8) * NDIM + gcol),
                           make_float2(acc[mt][nt8][2], acc[mt][nt8][3]));
#pragma unroll
                    for (int q = 0; q < 4; ++q) acc[mt][nt8][q] = 0.0f;
                }
            }
            rt_c += RTSTRIDE;
        }
    }
}

extern "C" void kernel_launch(void* const* d_in, const int* in_sizes, int n_in,
                              void* d_out, int out_size) {
    const float* x = (const float*)d_in[0];   // [65536, 512]
    const float* W = (const float*)d_in[1];   // [512, 64]
    float* out = (float*)d_out;               // [65536, 64]

    cudaFuncSetAttribute(NN_57844619543085_kernel,
                         cudaFuncAttributeMaxDynamicSharedMemorySize, SMEM_TOTAL);

    NN_57844619543085_kernel<<<GRID, THREADS, SMEM_TOTAL>>>(x, W, out);
}

// round 17
// speedup vs baseline: 1.0611x; 1.0611x over previous
#include <cuda_runtime.h>
#include <cuda_fp16.h>
#include <stdint.h>

// out[B,N] = x[B,K] @ W[K,N];  B=65536, K=512, N=64, fp32.
// Persistent-CTA fp16 HMMA (norm rel_err ~3e-4 < 1e-3).
// grid=#SMs, 512 thr (16 warps), warp-flat 16-row tiles, per-warp private
// 5-deep cp.async pipeline. R16: k permuted within each 16-block (pi applied
// to BOTH x-fragment slots and W prologue) so the A fragment's 16B are
// contiguous -> 4x LDS.128 instead of 8x LDS.64 per half-chunk; layout is
// conflict-free by construction (no XOR swizzle).

#define BATCH   65536
#define KDIM    512
#define NDIM    64
#define NTILES  (BATCH / 16)   // 4096
#define THREADS 512
#define NSTAGE  5

#define SM_W    0              // 64KB fp16 swizzled+permuted W
#define SM_X    65536          // warp w slot s: + (w*NSTAGE+s)*2048
#define SMEM_TOTAL (65536 + 16 * NSTAGE * 2048)   // 229376

__device__ __forceinline__ void mma_f16(float* d, const uint32_t* a, const uint32_t* b) {
    asm volatile(
        "mma.sync.aligned.m16n8k16.row.col.f32.f16.f16.f32 "
        "{%0,%1,%2,%3}, {%4,%5,%6,%7}, {%8,%9}, {%0,%1,%2,%3};\n"
        : "+f"(d[0]), "+f"(d[1]), "+f"(d[2]), "+f"(d[3])
        : "r"(a[0]), "r"(a[1]), "r"(a[2]), "r"(a[3]), "r"(b[0]), "r"(b[1]));
}

__device__ __forceinline__ void ldsm_x4(uint32_t* r, uint32_t saddr) {
    asm volatile("ldmatrix.sync.aligned.m8n8.x4.shared.b16 {%0,%1,%2,%3}, [%4];"
        : "=r"(r[0]), "=r"(r[1]), "=r"(r[2]), "=r"(r[3]) : "r"(saddr));
}

__device__ __forceinline__ void cpasync16(uint32_t saddr, const void* gptr) {
    asm volatile("cp.async.cg.shared.global [%0], [%1], 16;\n"
        :: "r"(saddr), "l"(gptr));
}
#define CP_COMMIT()  asm volatile("cp.async.commit_group;\n" ::: "memory")
#define CP_WAIT(N)   asm volatile("cp.async.wait_group %0;\n" :: "n"(N) : "memory")

__device__ __forceinline__ uint32_t cvt2f(float a, float b) {
    __half2 h = __floats2half2_rn(a, b);
    return *reinterpret_cast<uint32_t*>(&h);
}

__device__ __forceinline__ float4 lds128(uint32_t saddr) {
    float4 v;
    asm volatile("ld.shared.v4.f32 {%0,%1,%2,%3}, [%4];"
        : "=f"(v.x), "=f"(v.y), "=f"(v.z), "=f"(v.w) : "r"(saddr));
    return v;
}

__global__ __launch_bounds__(THREADS, 1)
void NN_57844619543085_kernel(const float* __restrict__ x,
                              const float* __restrict__ W,
                              float* __restrict__ out) {
    extern __shared__ __align__(1024) unsigned char sm[];
    const uint32_t smb = (uint32_t)__cvta_generic_to_shared(sm);

    const int t    = threadIdx.x;
    const int lane = t & 31;
    const int warp = t >> 5;
    const int G    = gridDim.x;

    // ---- warp's tile sequence ----
    const int rt0      = warp * G + blockIdx.x;
    const int rtstride = 16 * G;
    const int nt       = (NTILES - 1 - rt0) / rtstride + 1;
    const int npairs   = nt * 8;
    const int total    = nt * 16;

    // ---- fill addressing (new permute-friendly layout) ----
    // lane decomposition: q=l&3 (16B granule), r01=(l>>2)&1, jj=(l>>3)&1, rq=l>>4
    // stage offset(row, j, q) = (row>>1)*256 + j*128 + (row&1)*64 + q*16
    const int q_    = lane & 3;
    const int r01   = (lane >> 2) & 1;
    const int jj    = (lane >> 3) & 1;
    const int rq    = lane >> 4;
    const uint32_t fill_off = (uint32_t)rq * 256 + (uint32_t)jj * 128
                            + (uint32_t)r01 * 64 + (uint32_t)q_ * 16;
    const uint32_t xw = smb + SM_X + warp * (NSTAGE * 2048);

    // gmem: row (r01 + 2*rq) of tile, k-bytes jj*64 + q*16 within 32k half-chunk
    const float* fsrc = x + ((size_t)rt0 * 16 + r01 + 2 * rq) * KDIM
                          + jj * 16 + q_ * 4;
    int h_f = 0, sf = 0, ff = 0;
    const size_t tile_jump = (size_t)rtstride * 16 * KDIM;

#define ADV()                                                                  \
    {                                                                          \
        if (ff < total) {                                                      \
            uint32_t d_ = xw + sf * 2048 + fill_off;                           \
            const float* s_ = fsrc + h_f * 32;                                 \
            cpasync16(d_,        s_);                                          \
            cpasync16(d_ + 512,  s_ + 4 * KDIM);                               \
            cpasync16(d_ + 1024, s_ + 8 * KDIM);                               \
            cpasync16(d_ + 1536, s_ + 12 * KDIM);                              \
        }                                                                      \
        CP_COMMIT();                                                           \
        ++ff; sf = (sf == NSTAGE - 1) ? 0 : sf + 1;                            \
        if (++h_f == 16) { h_f = 0; fsrc += tile_jump; }                       \
    }

    // ---- prologue: 5 stages in flight ----
    ADV(); ADV(); ADV(); ADV(); ADV();

    // ---- W conversion with k-permute: position c holds W[pi(c)] ----
    // pi within each 16-block: slot 2u -> 4u, 2u+1 -> 4u+1, 2u+8 -> 4u+2, 2u+9 -> 4u+3
    // iterate data-k groups of 4 (4u..4u+3): they land at positions (2u,2u+1) and (2u+8,2u+9)
    {
        const int wn_ = t & 63;
        const int wq_ = t >> 6;              // 0..7, 64 data-k each
        const uint32_t wrow = smb + SM_W + wn_ * 128;
        const int nsw = (wn_ & 7) << 4;
#pragma unroll 4
        for (int i = 0; i < 16; ++i) {
            int k = wq_ * 64 + i * 4;        // data-k group base (4u)
            float f0 = __ldg(&W[(k + 0) * NDIM + wn_]);
            float f1 = __ldg(&W[(k + 1) * NDIM + wn_]);
            float f2 = __ldg(&W[(k + 2) * NDIM + wn_]);
            float f3 = __ldg(&W[(k + 3) * NDIM + wn_]);
            uint32_t p0 = cvt2f(f0, f1);     // -> positions 2u, 2u+1
            uint32_t p1 = cvt2f(f2, f3);     // -> positions 2u+8, 2u+9
            int blkl = (k >> 4) & 3;         // local 16-block within 64-chunk
            int u    = (k >> 2) & 3;
            int c0   = blkl * 16 + 2 * u;    // local position 0..63
            uint32_t chunk = (uint32_t)(k >> 6) * 8192;
            uint32_t b0 = chunk + (uint32_t)((c0 * 2) ^ nsw);
            uint32_t b1 = chunk + (uint32_t)(((c0 + 8) * 2) ^ nsw);
            asm volatile("st.shared.b32 [%0], %1;" :: "r"(wrow + b0), "r"(p0) : "memory");
            asm volatile("st.shared.b32 [%0], %1;" :: "r"(wrow + b1), "r"(p1) : "memory");
        }
    }

    // ---- consume addressing: one LDS.128 per (j, row-half) ----
    const int rhat = lane >> 2;              // 0..7
    const uint32_t cbase = (uint32_t)(rhat >> 1) * 256
                         + (uint32_t)(rhat & 1) * 64
                         + (uint32_t)(lane & 3) * 16;

    const int sub  = lane >> 3;
    const int lrow = lane & 7;

    float acc[8][4];
#pragma unroll
    for (int nt8 = 0; nt8 < 8; ++nt8)
#pragma unroll
        for (int q2 = 0; q2 < 4; ++q2) acc[nt8][q2] = 0.0f;

    __syncthreads();   // W tile visible CTA-wide

#define HALF(WB, KS0, KS1)                                                     \
    {                                                                          \
        CP_WAIT(NSTAGE - 1);                                                   \
        __syncwarp();                                                          \
        const uint32_t xb = xw + slot * 2048;                                  \
        uint32_t a0[4], a1[4];                                                 \
        { float4 v = lds128(xb + cbase);                                       \
          a0[0] = cvt2f(v.x, v.y); a0[2] = cvt2f(v.z, v.w); }                  \
        { float4 v = lds128(xb + cbase + 1024);                                \
          a0[1] = cvt2f(v.x, v.y); a0[3] = cvt2f(v.z, v.w); }                  \
        { float4 v = lds128(xb + cbase + 128);                                 \
          a1[0] = cvt2f(v.x, v.y); a1[2] = cvt2f(v.z, v.w); }                  \
        { float4 v = lds128(xb + cbase + 128 + 1024);                          \
          a1[1] = cvt2f(v.x, v.y); a1[3] = cvt2f(v.z, v.w); }                  \
        ADV();                                                                 \
        uint32_t b[8][2];                                                      \
        _Pragma("unroll")                                                      \
        for (int p = 0; p < 4; ++p) {                                          \
            int n = (2 * p + (sub >> 1)) * 8 + lrow;                           \
            uint32_t boff = (uint32_t)n * 128                                  \
                          + (((KS0) * 32 + (sub & 1) * 16) ^ (lrow << 4));     \
            uint32_t tmp[4];                                                   \
            ldsm_x4(tmp, (WB) + boff);                                         \
            b[2*p][0]   = tmp[0]; b[2*p][1]   = tmp[1];                        \
            b[2*p+1][0] = tmp[2]; b[2*p+1][1] = tmp[3];                        \
        }                                                                      \
        _Pragma("unroll")                                                      \
        for (int nt8 = 0; nt8 < 8; ++nt8) mma_f16(acc[nt8], a0, b[nt8]);       \
        _Pragma("unroll")                                                      \
        for (int p = 0; p < 4; ++p) {                                          \
            int n = (2 * p + (sub >> 1)) * 8 + lrow;                           \
            uint32_t boff = (uint32_t)n * 128                                  \
                          + (((KS1) * 32 + (sub & 1) * 16) ^ (lrow << 4));     \
            uint32_t tmp[4];                                                   \
            ldsm_x4(tmp, (WB) + boff);                                         \
            b[2*p][0]   = tmp[0]; b[2*p][1]   = tmp[1];                        \
            b[2*p+1][0] = tmp[2]; b[2*p+1][1] = tmp[3];                        \
        }                                                                      \
        _Pragma("unroll")                                                      \
        for (int nt8 = 0; nt8 < 8; ++nt8) mma_f16(acc[nt8], a1, b[nt8]);       \
        slot = (slot == NSTAGE - 1) ? 0 : slot + 1;                            \
    }

    int rt_c = rt0;
    int slot = 0;
#pragma unroll 1
    for (int f2 = 0; f2 < npairs; ++f2) {
        const uint32_t wbase = smb + SM_W + (uint32_t)(f2 & 7) * 8192;

        HALF(wbase, 0, 1);
        HALF(wbase, 2, 3);

        if ((f2 & 7) == 7) {
            const int arow = rt_c * 16 + (lane >> 2);
#pragma unroll
            for (int nt8 = 0; nt8 < 8; ++nt8) {
                int gcol = nt8 * 8 + (lane & 3) * 2;
                __stcs((float2*)(out + (size_t)arow * NDIM + gcol),
                       make_float2(acc[nt8][0], acc[nt8][1]));
                __stcs((float2*)(out + (size_t)(arow + 8) * NDIM + gcol),
                       make_float2(acc[nt8][2], acc[nt8][3]));
#pragma unroll
                for (int q2 = 0; q2 < 4; ++q2) acc[nt8][q2] = 0.0f;
            }
            rt_c += rtstride;
        }
    }
}

extern "C" void kernel_launch(void* const* d_in, const int* in_sizes, int n_in,
                              void* d_out, int out_size) {
    const float* x = (const float*)d_in[0];   // [65536, 512]
    const float* W = (const float*)d_in[1];   // [512, 64]
    float* out = (float*)d_out;               // [65536, 64]

    cudaFuncSetAttribute(NN_57844619543085_kernel,
                         cudaFuncAttributeMaxDynamicSharedMemorySize, SMEM_TOTAL);

    int sms = 148;
    cudaDeviceGetAttribute(&sms, cudaDevAttrMultiProcessorCount, 0);

    NN_57844619543085_kernel<<<sms, THREADS, SMEM_TOTAL>>>(x, W, out);
}